// round 14
// baseline (speedup 1.0000x reference)
#include <cuda_runtime.h>

// out = noised + 0.1f * noise   (elementwise, fp32)
// N = 64*3*512*512 = 50,331,648 (divisible by 4). Traffic floor 604 MB/pass.
//
// Measured landscape (bench dur_us = scoring metric; gap = bench - ncu kernel):
//   float4 plain 256thr/49152blk (R4/R10): kernel 81.5-82.3, bench 88.8-88.9, gap ~7
//   float4 plain 512thr/24576blk (R11):    kernel 84.3,      bench 88.45,     gap 4.1 <- best
//   v8 variants (R6/R8/R9):                kernel 79-81,     bench 90.2-90.5, gap 9-11
//   persistent grid-stride (R7):           bench 97.2
// Model: replay gap scales with CTA count (per-replay dispatch overhead) and
// with access-path exoticness. R12: continue the CTA-count lever -> block=1024,
// 12,288 CTAs. Predict gap ~3us; wins if gap shrink beats occupancy cost.

__global__ void __launch_bounds__(1024)
gaussian_noise_add_kernel(const float4* __restrict__ noised,
                          const float4* __restrict__ noise,
                          float4* __restrict__ out,
                          int n4)
{
    int i = blockIdx.x * blockDim.x + threadIdx.x;
    if (i < n4) {
        float4 a = noised[i];
        float4 b = noise[i];
        float4 r;
        r.x = fmaf(0.1f, b.x, a.x);
        r.y = fmaf(0.1f, b.y, a.y);
        r.z = fmaf(0.1f, b.z, a.z);
        r.w = fmaf(0.1f, b.w, a.w);
        out[i] = r;
    }
}

// Scalar tail kernel (defensive; n is divisible by 4 for this problem so it
// is not launched).
__global__ void gaussian_noise_tail_kernel(const float* __restrict__ noised,
                                           const float* __restrict__ noise,
                                           float* __restrict__ out,
                                           int start, int n)
{
    int i = start + blockIdx.x * blockDim.x + threadIdx.x;
    if (i < n) {
        out[i] = fmaf(0.1f, noise[i], noised[i]);
    }
}

extern "C" void kernel_launch(void* const* d_in, const int* in_sizes, int n_in,
                              void* d_out, int out_size)
{
    const float* noised = (const float*)d_in[0];
    const float* noise  = (const float*)d_in[1];
    float* out = (float*)d_out;
    int n = in_sizes[0];

    int n4 = n >> 2;
    if (n4 > 0) {
        int threads = 1024;
        int blocks = (n4 + threads - 1) / threads;
        gaussian_noise_add_kernel<<<blocks, threads>>>(
            (const float4*)noised, (const float4*)noise, (float4*)out, n4);
    }
    int rem = n - (n4 << 2);
    if (rem > 0) {
        gaussian_noise_tail_kernel<<<1, 256>>>(noised, noise, out, n4 << 2, n);
    }
}